// round 1
// baseline (speedup 1.0000x reference)
#include <cuda_runtime.h>
#include <cuda_bf16.h>

// XYLoss: out = (S1 / (B*H*W)) * S2
//   S1 = sum over pixels of [(t0+t1)*softplus(s1-s0) - t1*(s1-s0)], s_c = sigmoid(x_c)
//   S2 = sum(object_mask * box_loss_scale)
// Inputs (metadata order): object_mask[16,1,1024,1024], box_loss_scale[16,1,1024,1024],
//                          predict_xy[16,2,1024,1024], true_xy[16,2,1024,1024]  (all f32)
// Output: single f32 scalar.

#define HW_   (1024 * 1024)
#define B_    16
#define PIX_  (B_ * HW_)        // 16,777,216 pixels
#define NVEC_ (PIX_ / 4)        // float4 iterations

constexpr int BLOCKS  = 1184;   // 148 SMs * 8
constexpr int THREADS = 256;

__device__ float g_part1[BLOCKS];
__device__ float g_part2[BLOCKS];

__device__ __forceinline__ float sigmoid_fast(float x) {
    // 1 / (1 + e^-x): MUFU.EX2 + MUFU.RCP
    return __fdividef(1.0f, 1.0f + __expf(-x));
}

__device__ __forceinline__ float per_elem(float x0, float x1, float t0, float t1) {
    float s0 = sigmoid_fast(x0);
    float s1 = sigmoid_fast(x1);
    float d  = s1 - s0;                      // in (-1, 1)
    float sp = __logf(1.0f + __expf(d));     // softplus(d), well-conditioned here
    return (t0 + t1) * sp - t1 * d;
}

__global__ __launch_bounds__(THREADS) void xyloss_main(
    const float* __restrict__ mask,
    const float* __restrict__ scale,
    const float* __restrict__ pred,
    const float* __restrict__ truth)
{
    float acc1 = 0.0f;
    float acc2 = 0.0f;

    const int stride = gridDim.x * blockDim.x;
    for (int v = blockIdx.x * blockDim.x + threadIdx.x; v < NVEC_; v += stride) {
        int idx = v << 2;                    // pixel index (multiple of 4)
        int b   = idx >> 20;                 // HW_ = 2^20
        int i   = idx & (HW_ - 1);
        long base = (long)b * (2L * HW_) + i;

        float4 m  = *reinterpret_cast<const float4*>(mask  + idx);
        float4 sc = *reinterpret_cast<const float4*>(scale + idx);
        float4 x0 = *reinterpret_cast<const float4*>(pred  + base);
        float4 x1 = *reinterpret_cast<const float4*>(pred  + base + HW_);
        float4 t0 = *reinterpret_cast<const float4*>(truth + base);
        float4 t1 = *reinterpret_cast<const float4*>(truth + base + HW_);

        acc1 += per_elem(x0.x, x1.x, t0.x, t1.x);
        acc1 += per_elem(x0.y, x1.y, t0.y, t1.y);
        acc1 += per_elem(x0.z, x1.z, t0.z, t1.z);
        acc1 += per_elem(x0.w, x1.w, t0.w, t1.w);

        acc2 += m.x * sc.x + m.y * sc.y + m.z * sc.z + m.w * sc.w;
    }

    // Warp reduce
    #pragma unroll
    for (int off = 16; off > 0; off >>= 1) {
        acc1 += __shfl_xor_sync(0xFFFFFFFFu, acc1, off);
        acc2 += __shfl_xor_sync(0xFFFFFFFFu, acc2, off);
    }

    // Block reduce across 8 warps
    __shared__ float sh1[THREADS / 32];
    __shared__ float sh2[THREADS / 32];
    int wid = threadIdx.x >> 5;
    int lid = threadIdx.x & 31;
    if (lid == 0) { sh1[wid] = acc1; sh2[wid] = acc2; }
    __syncthreads();
    if (wid == 0) {
        float b1 = (lid < THREADS / 32) ? sh1[lid] : 0.0f;
        float b2 = (lid < THREADS / 32) ? sh2[lid] : 0.0f;
        #pragma unroll
        for (int off = 4; off > 0; off >>= 1) {
            b1 += __shfl_xor_sync(0xFFFFFFFFu, b1, off);
            b2 += __shfl_xor_sync(0xFFFFFFFFu, b2, off);
        }
        if (lid == 0) {
            g_part1[blockIdx.x] = b1;
            g_part2[blockIdx.x] = b2;
        }
    }
}

__global__ __launch_bounds__(THREADS) void xyloss_finalize(float* __restrict__ out)
{
    // Deterministic double-precision combine of BLOCKS partials.
    double a = 0.0, b = 0.0;
    for (int i = threadIdx.x; i < BLOCKS; i += THREADS) {
        a += (double)g_part1[i];
        b += (double)g_part2[i];
    }
    #pragma unroll
    for (int off = 16; off > 0; off >>= 1) {
        a += __shfl_xor_sync(0xFFFFFFFFu, a, off);
        b += __shfl_xor_sync(0xFFFFFFFFu, b, off);
    }
    __shared__ double da[THREADS / 32];
    __shared__ double db[THREADS / 32];
    int wid = threadIdx.x >> 5;
    int lid = threadIdx.x & 31;
    if (lid == 0) { da[wid] = a; db[wid] = b; }
    __syncthreads();
    if (threadIdx.x == 0) {
        double A = 0.0, Bb = 0.0;
        #pragma unroll
        for (int w = 0; w < THREADS / 32; w++) { A += da[w]; Bb += db[w]; }
        double loss = A / (double)PIX_;
        out[0] = (float)(loss * Bb);
    }
}

extern "C" void kernel_launch(void* const* d_in, const int* in_sizes, int n_in,
                              void* d_out, int out_size)
{
    const float* mask  = (const float*)d_in[0];
    const float* scale = (const float*)d_in[1];
    const float* pred  = (const float*)d_in[2];
    const float* truth = (const float*)d_in[3];
    float* out = (float*)d_out;

    xyloss_main<<<BLOCKS, THREADS>>>(mask, scale, pred, truth);
    xyloss_finalize<<<1, THREADS>>>(out);
}

// round 2
// speedup vs baseline: 1.0005x; 1.0005x over previous
#include <cuda_runtime.h>
#include <cuda_bf16.h>

// XYLoss: out = (S1 / (B*H*W)) * S2
//   S1 = sum over pixels of [(t0+t1)*softplus(s1-s0) - t1*(s1-s0)], s_c = sigmoid(x_c)
//   S2 = sum(object_mask * box_loss_scale)
// Single fused kernel: grid-stride streaming pass + fence/ticket last-block finalize.

#define HW_   (1024 * 1024)
#define B_    16
#define PIX_  (B_ * HW_)        // 16,777,216 pixels
#define NVEC_ (PIX_ / 4)        // float4 iterations

constexpr int BLOCKS  = 1184;   // 148 SMs * 8
constexpr int THREADS = 256;

__device__ float g_part1[BLOCKS];
__device__ float g_part2[BLOCKS];
__device__ unsigned int g_ticket;   // zero-initialized at module load; last block resets it

__device__ __forceinline__ float sigmoid_fast(float x) {
    return __fdividef(1.0f, 1.0f + __expf(-x));   // MUFU.EX2 + MUFU.RCP
}

__device__ __forceinline__ float per_elem(float x0, float x1, float t0, float t1) {
    float s0 = sigmoid_fast(x0);
    float s1 = sigmoid_fast(x1);
    float d  = s1 - s0;                      // in (-1, 1)
    float sp = __logf(1.0f + __expf(d));     // softplus(d), well-conditioned on (-1,1)
    return (t0 + t1) * sp - t1 * d;
}

__device__ __forceinline__ float4 ldcs4(const float* p) {
    return __ldcs(reinterpret_cast<const float4*>(p));
}

__global__ __launch_bounds__(THREADS) void xyloss_fused(
    const float* __restrict__ mask,
    const float* __restrict__ scale,
    const float* __restrict__ pred,
    const float* __restrict__ truth,
    float* __restrict__ out)
{
    float acc1 = 0.0f;
    float acc2 = 0.0f;

    const int stride = gridDim.x * blockDim.x;
    #pragma unroll 2
    for (int v = blockIdx.x * blockDim.x + threadIdx.x; v < NVEC_; v += stride) {
        int idx = v << 2;                    // pixel index (multiple of 4)
        int b   = idx >> 20;                 // HW_ = 2^20
        int i   = idx & (HW_ - 1);
        long base = (long)b * (2L * HW_) + i;

        float4 m  = ldcs4(mask  + idx);
        float4 sc = ldcs4(scale + idx);
        float4 x0 = ldcs4(pred  + base);
        float4 x1 = ldcs4(pred  + base + HW_);
        float4 t0 = ldcs4(truth + base);
        float4 t1 = ldcs4(truth + base + HW_);

        acc1 += per_elem(x0.x, x1.x, t0.x, t1.x);
        acc1 += per_elem(x0.y, x1.y, t0.y, t1.y);
        acc1 += per_elem(x0.z, x1.z, t0.z, t1.z);
        acc1 += per_elem(x0.w, x1.w, t0.w, t1.w);

        acc2 += m.x * sc.x + m.y * sc.y + m.z * sc.z + m.w * sc.w;
    }

    // Warp reduce
    #pragma unroll
    for (int off = 16; off > 0; off >>= 1) {
        acc1 += __shfl_xor_sync(0xFFFFFFFFu, acc1, off);
        acc2 += __shfl_xor_sync(0xFFFFFFFFu, acc2, off);
    }

    // Block reduce across 8 warps
    __shared__ float sh1[THREADS / 32];
    __shared__ float sh2[THREADS / 32];
    __shared__ bool  s_last;
    int wid = threadIdx.x >> 5;
    int lid = threadIdx.x & 31;
    if (lid == 0) { sh1[wid] = acc1; sh2[wid] = acc2; }
    __syncthreads();
    if (threadIdx.x == 0) {
        float b1 = 0.0f, b2 = 0.0f;
        #pragma unroll
        for (int w = 0; w < THREADS / 32; w++) { b1 += sh1[w]; b2 += sh2[w]; }
        g_part1[blockIdx.x] = b1;
        g_part2[blockIdx.x] = b2;
        __threadfence();
        unsigned int t = atomicInc(&g_ticket, BLOCKS - 1);   // wraps to 0 at BLOCKS-1
        s_last = (t == BLOCKS - 1);                          // last arriving block; counter now reset
    }
    __syncthreads();

    if (s_last) {
        // Deterministic double-precision combine of all BLOCKS partials.
        double a = 0.0, b = 0.0;
        for (int i = threadIdx.x; i < BLOCKS; i += THREADS) {
            a += (double)g_part1[i];
            b += (double)g_part2[i];
        }
        #pragma unroll
        for (int off = 16; off > 0; off >>= 1) {
            a += __shfl_xor_sync(0xFFFFFFFFu, a, off);
            b += __shfl_xor_sync(0xFFFFFFFFu, b, off);
        }
        __shared__ double da[THREADS / 32];
        __shared__ double db[THREADS / 32];
        if (lid == 0) { da[wid] = a; db[wid] = b; }
        __syncthreads();
        if (threadIdx.x == 0) {
            double A = 0.0, Bb = 0.0;
            #pragma unroll
            for (int w = 0; w < THREADS / 32; w++) { A += da[w]; Bb += db[w]; }
            double loss = A / (double)PIX_;
            out[0] = (float)(loss * Bb);
        }
    }
}

extern "C" void kernel_launch(void* const* d_in, const int* in_sizes, int n_in,
                              void* d_out, int out_size)
{
    const float* mask  = (const float*)d_in[0];
    const float* scale = (const float*)d_in[1];
    const float* pred  = (const float*)d_in[2];
    const float* truth = (const float*)d_in[3];
    float* out = (float*)d_out;

    xyloss_fused<<<BLOCKS, THREADS>>>(mask, scale, pred, truth, out);
}

// round 3
// speedup vs baseline: 1.0172x; 1.0167x over previous
#include <cuda_runtime.h>
#include <cuda_bf16.h>

// XYLoss: out = (S1 / (B*H*W)) * S2
//   S1 = sum over pixels of [(t0+t1)*softplus(s1-s0) - t1*(s1-s0)], s_c = sigmoid(x_c)
//   S2 = sum(object_mask * box_loss_scale)
// Single fused kernel: grid-stride streaming pass + fence/ticket last-block finalize.
// Grid sized to EXACTLY one occupancy wave: 36 regs -> 7 blocks/SM -> 148*7 = 1036.

#define HW_   (1024u * 1024u)
#define B_    16u
#define PIX_  (B_ * HW_)        // 16,777,216 pixels
#define NVEC_ (PIX_ / 4u)       // float4 iterations

constexpr int BLOCKS  = 1036;   // 148 SMs * 7 resident blocks (36-reg limit) = one wave
constexpr int THREADS = 256;

__device__ float g_part1[BLOCKS];
__device__ float g_part2[BLOCKS];
__device__ unsigned int g_ticket;   // zero-init at load; last block wraps it back to 0

__device__ __forceinline__ float sigmoid_fast(float x) {
    return __fdividef(1.0f, 1.0f + __expf(-x));   // MUFU.EX2 + MUFU.RCP
}

__device__ __forceinline__ float per_elem(float x0, float x1, float t0, float t1) {
    float s0 = sigmoid_fast(x0);
    float s1 = sigmoid_fast(x1);
    float d  = s1 - s0;                      // in (-1, 1)
    float sp = __logf(1.0f + __expf(d));     // softplus(d), well-conditioned on (-1,1)
    return (t0 + t1) * sp - t1 * d;
}

__device__ __forceinline__ float4 ldcs4(const float* p) {
    return __ldcs(reinterpret_cast<const float4*>(p));
}

__global__ __launch_bounds__(THREADS) void xyloss_fused(
    const float* __restrict__ mask,
    const float* __restrict__ scale,
    const float* __restrict__ pred,
    const float* __restrict__ truth,
    float* __restrict__ out)
{
    float acc1 = 0.0f;
    float acc2 = 0.0f;

    const unsigned int stride = (unsigned int)(gridDim.x * blockDim.x);
    for (unsigned int v = blockIdx.x * blockDim.x + threadIdx.x; v < NVEC_; v += stride) {
        unsigned int idx  = v << 2;                   // pixel index (multiple of 4)
        unsigned int b    = idx >> 20;                // HW_ = 2^20
        unsigned int i    = idx & (HW_ - 1u);
        unsigned int base = (b << 21) + i;            // b * 2*HW_ + i  (max ~32.5M < 2^31)

        float4 m  = ldcs4(mask  + idx);
        float4 sc = ldcs4(scale + idx);
        float4 x0 = ldcs4(pred  + base);
        float4 x1 = ldcs4(pred  + base + HW_);
        float4 t0 = ldcs4(truth + base);
        float4 t1 = ldcs4(truth + base + HW_);

        acc1 += per_elem(x0.x, x1.x, t0.x, t1.x);
        acc1 += per_elem(x0.y, x1.y, t0.y, t1.y);
        acc1 += per_elem(x0.z, x1.z, t0.z, t1.z);
        acc1 += per_elem(x0.w, x1.w, t0.w, t1.w);

        acc2 += m.x * sc.x + m.y * sc.y + m.z * sc.z + m.w * sc.w;
    }

    // Warp reduce
    #pragma unroll
    for (int off = 16; off > 0; off >>= 1) {
        acc1 += __shfl_xor_sync(0xFFFFFFFFu, acc1, off);
        acc2 += __shfl_xor_sync(0xFFFFFFFFu, acc2, off);
    }

    // Block reduce across 8 warps
    __shared__ float sh1[THREADS / 32];
    __shared__ float sh2[THREADS / 32];
    __shared__ bool  s_last;
    int wid = threadIdx.x >> 5;
    int lid = threadIdx.x & 31;
    if (lid == 0) { sh1[wid] = acc1; sh2[wid] = acc2; }
    __syncthreads();
    if (threadIdx.x == 0) {
        float b1 = 0.0f, b2 = 0.0f;
        #pragma unroll
        for (int w = 0; w < THREADS / 32; w++) { b1 += sh1[w]; b2 += sh2[w]; }
        g_part1[blockIdx.x] = b1;
        g_part2[blockIdx.x] = b2;
        __threadfence();
        unsigned int t = atomicInc(&g_ticket, BLOCKS - 1);   // wraps to 0 at BLOCKS-1
        s_last = (t == BLOCKS - 1);                          // last arriving block; counter reset
    }
    __syncthreads();

    if (s_last) {
        // Deterministic double-precision combine of all BLOCKS partials.
        double a = 0.0, b = 0.0;
        for (int i = threadIdx.x; i < BLOCKS; i += THREADS) {
            a += (double)g_part1[i];
            b += (double)g_part2[i];
        }
        #pragma unroll
        for (int off = 16; off > 0; off >>= 1) {
            a += __shfl_xor_sync(0xFFFFFFFFu, a, off);
            b += __shfl_xor_sync(0xFFFFFFFFu, b, off);
        }
        __shared__ double da[THREADS / 32];
        __shared__ double db[THREADS / 32];
        if (lid == 0) { da[wid] = a; db[wid] = b; }
        __syncthreads();
        if (threadIdx.x == 0) {
            double A = 0.0, Bb = 0.0;
            #pragma unroll
            for (int w = 0; w < THREADS / 32; w++) { A += da[w]; Bb += db[w]; }
            double loss = A / (double)PIX_;
            out[0] = (float)(loss * Bb);
        }
    }
}

extern "C" void kernel_launch(void* const* d_in, const int* in_sizes, int n_in,
                              void* d_out, int out_size)
{
    const float* mask  = (const float*)d_in[0];
    const float* scale = (const float*)d_in[1];
    const float* pred  = (const float*)d_in[2];
    const float* truth = (const float*)d_in[3];
    float* out = (float*)d_out;

    xyloss_fused<<<BLOCKS, THREADS>>>(mask, scale, pred, truth, out);
}

// round 4
// speedup vs baseline: 1.0380x; 1.0205x over previous
#include <cuda_runtime.h>
#include <cuda_bf16.h>

// XYLoss: out = (S1 / (B*H*W)) * S2
//   S1 = sum over pixels of [(t0+t1)*softplus(s1-s0) - t1*(s1-s0)], s_c = sigmoid(x_c)
//   S2 = sum(object_mask * box_loss_scale)
// Single fused kernel: grid-stride streaming pass + fence/ticket last-block finalize.
// 32 regs (pinned via __launch_bounds__) -> 8 blocks/SM -> grid 148*8 = 1184 = one full wave.

#define HW_   (1024u * 1024u)
#define B_    16u
#define PIX_  (B_ * HW_)        // 16,777,216 pixels
#define NVEC_ (PIX_ / 4u)       // float4 iterations

constexpr int BLOCKS  = 1184;   // 148 SMs * 8 resident blocks (32-reg limit) = one wave
constexpr int THREADS = 256;

__device__ float g_part1[BLOCKS];
__device__ float g_part2[BLOCKS];
__device__ unsigned int g_ticket;   // zero-init at load; last block wraps it back to 0

__device__ __forceinline__ float sigmoid_fast(float x) {
    return __fdividef(1.0f, 1.0f + __expf(-x));   // MUFU.EX2 + MUFU.RCP
}

__device__ __forceinline__ float per_elem(float x0, float x1, float t0, float t1) {
    float s0 = sigmoid_fast(x0);
    float s1 = sigmoid_fast(x1);
    float d  = s1 - s0;                      // in (-1, 1)
    float sp = __logf(1.0f + __expf(d));     // softplus(d), well-conditioned on (-1,1)
    return (t0 + t1) * sp - t1 * d;
}

__device__ __forceinline__ float4 ldcs4(const float* p) {
    return __ldcs(reinterpret_cast<const float4*>(p));
}

__global__ __launch_bounds__(THREADS, 8) void xyloss_fused(
    const float* __restrict__ mask,
    const float* __restrict__ scale,
    const float* __restrict__ pred,
    const float* __restrict__ truth,
    float* __restrict__ out)
{
    float acc1 = 0.0f;
    float acc2 = 0.0f;

    const unsigned int stride = (unsigned int)(gridDim.x * blockDim.x);
    for (unsigned int v = blockIdx.x * blockDim.x + threadIdx.x; v < NVEC_; v += stride) {
        unsigned int idx  = v << 2;                   // pixel index (multiple of 4)
        unsigned int b    = idx >> 20;                // HW_ = 2^20
        unsigned int i    = idx & (HW_ - 1u);
        unsigned int base = (b << 21) + i;            // b * 2*HW_ + i  (max ~32.5M < 2^31)

        float4 m  = ldcs4(mask  + idx);
        float4 sc = ldcs4(scale + idx);
        float4 x0 = ldcs4(pred  + base);
        float4 x1 = ldcs4(pred  + base + HW_);
        float4 t0 = ldcs4(truth + base);
        float4 t1 = ldcs4(truth + base + HW_);

        acc1 += per_elem(x0.x, x1.x, t0.x, t1.x);
        acc1 += per_elem(x0.y, x1.y, t0.y, t1.y);
        acc1 += per_elem(x0.z, x1.z, t0.z, t1.z);
        acc1 += per_elem(x0.w, x1.w, t0.w, t1.w);

        acc2 += m.x * sc.x + m.y * sc.y + m.z * sc.z + m.w * sc.w;
    }

    // Warp reduce
    #pragma unroll
    for (int off = 16; off > 0; off >>= 1) {
        acc1 += __shfl_xor_sync(0xFFFFFFFFu, acc1, off);
        acc2 += __shfl_xor_sync(0xFFFFFFFFu, acc2, off);
    }

    // Block reduce across 8 warps
    __shared__ float sh1[THREADS / 32];
    __shared__ float sh2[THREADS / 32];
    __shared__ bool  s_last;
    int wid = threadIdx.x >> 5;
    int lid = threadIdx.x & 31;
    if (lid == 0) { sh1[wid] = acc1; sh2[wid] = acc2; }
    __syncthreads();
    if (threadIdx.x == 0) {
        float b1 = 0.0f, b2 = 0.0f;
        #pragma unroll
        for (int w = 0; w < THREADS / 32; w++) { b1 += sh1[w]; b2 += sh2[w]; }
        g_part1[blockIdx.x] = b1;
        g_part2[blockIdx.x] = b2;
        __threadfence();
        unsigned int t = atomicInc(&g_ticket, BLOCKS - 1);   // wraps to 0 at BLOCKS-1
        s_last = (t == BLOCKS - 1);                          // last arriving block; counter reset
    }
    __syncthreads();

    if (s_last) {
        // Deterministic double-precision combine of all BLOCKS partials.
        double a = 0.0, b = 0.0;
        for (int i = threadIdx.x; i < BLOCKS; i += THREADS) {
            a += (double)g_part1[i];
            b += (double)g_part2[i];
        }
        #pragma unroll
        for (int off = 16; off > 0; off >>= 1) {
            a += __shfl_xor_sync(0xFFFFFFFFu, a, off);
            b += __shfl_xor_sync(0xFFFFFFFFu, b, off);
        }
        __shared__ double da[THREADS / 32];
        __shared__ double db[THREADS / 32];
        if (lid == 0) { da[wid] = a; db[wid] = b; }
        __syncthreads();
        if (threadIdx.x == 0) {
            double A = 0.0, Bb = 0.0;
            #pragma unroll
            for (int w = 0; w < THREADS / 32; w++) { A += da[w]; Bb += db[w]; }
            double loss = A / (double)PIX_;
            out[0] = (float)(loss * Bb);
        }
    }
}

extern "C" void kernel_launch(void* const* d_in, const int* in_sizes, int n_in,
                              void* d_out, int out_size)
{
    const float* mask  = (const float*)d_in[0];
    const float* scale = (const float*)d_in[1];
    const float* pred  = (const float*)d_in[2];
    const float* truth = (const float*)d_in[3];
    float* out = (float*)d_out;

    xyloss_fused<<<BLOCKS, THREADS>>>(mask, scale, pred, truth, out);
}

// round 5
// speedup vs baseline: 1.0421x; 1.0039x over previous
#include <cuda_runtime.h>
#include <cuda_bf16.h>

// XYLoss: out = (S1 / (B*H*W)) * S2
//   S1 = sum over pixels of [(t0+t1)*softplus(s1-s0) - t1*(s1-s0)], s_c = sigmoid(x_c)
//   S2 = sum(object_mask * box_loss_scale)
// Single fused kernel. 42-reg budget (6 blocks/SM) so all 6 float4 loads per
// iteration can be front-batched (live simultaneously) -> higher per-warp MLP.

#define HW_   (1024u * 1024u)
#define B_    16u
#define PIX_  (B_ * HW_)        // 16,777,216 pixels
#define NVEC_ (PIX_ / 4u)       // float4 iterations

constexpr int BLOCKS  = 888;    // 148 SMs * 6 resident blocks (42-reg limit) = one wave
constexpr int THREADS = 256;

__device__ float g_part1[BLOCKS];
__device__ float g_part2[BLOCKS];
__device__ unsigned int g_ticket;   // zero-init at load; last block wraps it back to 0

__device__ __forceinline__ float sigmoid_fast(float x) {
    return __fdividef(1.0f, 1.0f + __expf(-x));   // MUFU.EX2 + MUFU.RCP
}

__device__ __forceinline__ float per_elem(float x0, float x1, float t0, float t1) {
    float s0 = sigmoid_fast(x0);
    float s1 = sigmoid_fast(x1);
    float d  = s1 - s0;                      // in (-1, 1)
    float sp = __logf(1.0f + __expf(d));     // softplus(d), well-conditioned on (-1,1)
    return (t0 + t1) * sp - t1 * d;
}

__device__ __forceinline__ float4 ldcs4(const float* p) {
    return __ldcs(reinterpret_cast<const float4*>(p));
}

__global__ __launch_bounds__(THREADS, 6) void xyloss_fused(
    const float* __restrict__ mask,
    const float* __restrict__ scale,
    const float* __restrict__ pred,
    const float* __restrict__ truth,
    float* __restrict__ out)
{
    float acc1 = 0.0f;
    float acc2 = 0.0f;

    const unsigned int stride = (unsigned int)(gridDim.x * blockDim.x);
    #pragma unroll 2
    for (unsigned int v = blockIdx.x * blockDim.x + threadIdx.x; v < NVEC_; v += stride) {
        unsigned int idx  = v << 2;                       // pixel index (multiple of 4)
        unsigned int base = idx + (idx & ~(HW_ - 1u));    // = idx + b*HW_  (b = idx>>20)

        // Front-batch ALL loads so they are in flight together.
        float4 m  = ldcs4(mask  + idx);
        float4 sc = ldcs4(scale + idx);
        float4 x0 = ldcs4(pred  + base);
        float4 x1 = ldcs4(pred  + base + HW_);
        float4 t0 = ldcs4(truth + base);
        float4 t1 = ldcs4(truth + base + HW_);

        acc2 += m.x * sc.x + m.y * sc.y + m.z * sc.z + m.w * sc.w;

        acc1 += per_elem(x0.x, x1.x, t0.x, t1.x);
        acc1 += per_elem(x0.y, x1.y, t0.y, t1.y);
        acc1 += per_elem(x0.z, x1.z, t0.z, t1.z);
        acc1 += per_elem(x0.w, x1.w, t0.w, t1.w);
    }

    // Warp reduce
    #pragma unroll
    for (int off = 16; off > 0; off >>= 1) {
        acc1 += __shfl_xor_sync(0xFFFFFFFFu, acc1, off);
        acc2 += __shfl_xor_sync(0xFFFFFFFFu, acc2, off);
    }

    // Block reduce across 8 warps
    __shared__ float sh1[THREADS / 32];
    __shared__ float sh2[THREADS / 32];
    __shared__ bool  s_last;
    int wid = threadIdx.x >> 5;
    int lid = threadIdx.x & 31;
    if (lid == 0) { sh1[wid] = acc1; sh2[wid] = acc2; }
    __syncthreads();
    if (threadIdx.x == 0) {
        float b1 = 0.0f, b2 = 0.0f;
        #pragma unroll
        for (int w = 0; w < THREADS / 32; w++) { b1 += sh1[w]; b2 += sh2[w]; }
        g_part1[blockIdx.x] = b1;
        g_part2[blockIdx.x] = b2;
        __threadfence();
        unsigned int t = atomicInc(&g_ticket, BLOCKS - 1);   // wraps to 0 at BLOCKS-1
        s_last = (t == BLOCKS - 1);                          // last arriving block; counter reset
    }
    __syncthreads();

    if (s_last) {
        // Deterministic double-precision combine of all BLOCKS partials.
        double a = 0.0, b = 0.0;
        for (int i = threadIdx.x; i < BLOCKS; i += THREADS) {
            a += (double)g_part1[i];
            b += (double)g_part2[i];
        }
        #pragma unroll
        for (int off = 16; off > 0; off >>= 1) {
            a += __shfl_xor_sync(0xFFFFFFFFu, a, off);
            b += __shfl_xor_sync(0xFFFFFFFFu, b, off);
        }
        __shared__ double da[THREADS / 32];
        __shared__ double db[THREADS / 32];
        if (lid == 0) { da[wid] = a; db[wid] = b; }
        __syncthreads();
        if (threadIdx.x == 0) {
            double A = 0.0, Bb = 0.0;
            #pragma unroll
            for (int w = 0; w < THREADS / 32; w++) { A += da[w]; Bb += db[w]; }
            double loss = A / (double)PIX_;
            out[0] = (float)(loss * Bb);
        }
    }
}

extern "C" void kernel_launch(void* const* d_in, const int* in_sizes, int n_in,
                              void* d_out, int out_size)
{
    const float* mask  = (const float*)d_in[0];
    const float* scale = (const float*)d_in[1];
    const float* pred  = (const float*)d_in[2];
    const float* truth = (const float*)d_in[3];
    float* out = (float*)d_out;

    xyloss_fused<<<BLOCKS, THREADS>>>(mask, scale, pred, truth, out);
}